// round 11
// baseline (speedup 1.0000x reference)
#include <cuda_runtime.h>
#include <math.h>

#define KE_CONST 14.3996f
#define MAX_ATOMS 131072

// Scratch (no allocations allowed in kernel_launch)
__device__ float4 g_packed[MAX_ATOMS];   // x, y, z, Zf per atom
__device__ float  g_zpow[64];            // Z^softplus(a_exp) LUT
__device__ float  g_params[16];          // [0]=1/an, [1..4]=coeffs, [5..8]=exps, [9]=0.5*KE*rep_scale

__device__ __forceinline__ float softplus_f(float x) {
    return (x > 20.0f) ? x : log1pf(expf(x));
}

__global__ void prepass_kernel(const float* __restrict__ R,
                               const int*   __restrict__ Z,
                               const float* __restrict__ a_exp,
                               const float* __restrict__ a_num,
                               const float* __restrict__ coefficients,
                               const float* __restrict__ exponents,
                               const float* __restrict__ rep_scale,
                               float* __restrict__ out,
                               int nAtoms) {
    int i = blockIdx.x * blockDim.x + threadIdx.x;
    if (i < nAtoms) {
        float4 p;
        p.x = R[3 * i + 0];
        p.y = R[3 * i + 1];
        p.z = R[3 * i + 2];
        p.w = (float)Z[i];
        g_packed[i] = p;
    }
    // Parallel Z^ae LUT
    if (i < 64) {
        float ae = softplus_f(a_exp[0]);
        g_zpow[i] = (i == 0) ? 0.0f : powf((float)i, ae);
    }
    if (i == 0) {
        out[0] = 0.0f;  // d_out is poisoned; zero before atomics
        g_params[0] = 1.0f / softplus_f(a_num[0]);
        #pragma unroll
        for (int k = 0; k < 4; ++k) {
            g_params[1 + k] = softplus_f(coefficients[k]);
            g_params[5 + k] = softplus_f(exponents[k]);
        }
        g_params[9] = 0.5f * KE_CONST * softplus_f(rep_scale[0]);
    }
}

// Champion configuration (stable across R7/R9/R10 re-benches):
//  - packed float4 atom records: 1 L1tex wavefront per gather (binding
//    resource: 12.8M random gathers ~= 86.5K wavefronts/SM ~= 44-48us floor)
//  - params in SMEM, read only inside the rare (<2%) live branch -> hot
//    gather path fits regs<=32 -> 8 CTAs x 256 = 64 warps/SM
//  - 4 edges/thread as two MLP=4 gather batches
//  - many short CTAs (6250 = 5.3 waves) for work-stealing backfill
//  - d2>=36 early-out kills ~98% of MUFU work (cutoff exactly zero there)
//  - NEW: max-L1 carveout (only 328B smem used) -> bigger L1D slice of the
//    1.6MB atom table -> more 32cyc hits replacing 234cyc L2 trips
// Measured-rejected: 32-warp/MLP-8 (R2), persistent grid (R5), block=128
// (R6), 8 edges/thread (R8).
__device__ __forceinline__ float edge_contrib(float4 pi, float4 pj, int ai, int aj,
                                              const float* __restrict__ s_zpow,
                                              const volatile float* s_par) {
    float dx = pj.x - pi.x;
    float dy = pj.y - pi.y;
    float dz = pj.z - pi.z;
    float d2 = fmaf(dx, dx, fmaf(dy, dy, dz * dz));
    if (d2 < 36.0f && ai != aj) {
        float dr = fmaxf(sqrtf(d2), 0.02f);
        float inv_dr = __fdividef(1.0f, dr);
        // cos(pi * dr / 6): pi/6 = 0.5235987755982988
        float ccut = 0.5f * (__cosf(dr * 0.5235987755982988f) + 1.0f);
        float adiv = s_zpow[(int)pi.w] + s_zpow[(int)pj.w];
        float dist = dr * adiv * s_par[0];
        float f = s_par[1] * __expf(-s_par[5] * dist)
                + s_par[2] * __expf(-s_par[6] * dist)
                + s_par[3] * __expf(-s_par[7] * dist)
                + s_par[4] * __expf(-s_par[8] * dist);
        return pi.w * pj.w * inv_dr * f * ccut;
    }
    return 0.0f;
}

__global__ __launch_bounds__(256, 8)
void edge_kernel(const int* __restrict__ idx_i,
                 const int* __restrict__ idx_j,
                 float* __restrict__ out,
                 int nQuad) {
    __shared__ float s_zpow[64];
    __shared__ float s_par[10];
    __shared__ float s_red[8];

    int tid = threadIdx.x;
    if (tid < 64) s_zpow[tid] = g_zpow[tid];
    if (tid < 10) s_par[tid] = g_params[tid];
    __syncthreads();

    float acc = 0.0f;
    int t = blockIdx.x * 256 + tid;

    if (t < nQuad) {
        int4 vi = __ldg(((const int4*)idx_i) + t);
        int4 vj = __ldg(((const int4*)idx_j) + t);

        // Batch of 4 gathers in flight before any compute
        {
            float4 pi0 = __ldg(&g_packed[vi.x]);
            float4 pj0 = __ldg(&g_packed[vj.x]);
            float4 pi1 = __ldg(&g_packed[vi.y]);
            float4 pj1 = __ldg(&g_packed[vj.y]);
            acc += edge_contrib(pi0, pj0, vi.x, vj.x, s_zpow, s_par);
            acc += edge_contrib(pi1, pj1, vi.y, vj.y, s_zpow, s_par);
        }
        {
            float4 pi2 = __ldg(&g_packed[vi.z]);
            float4 pj2 = __ldg(&g_packed[vj.z]);
            float4 pi3 = __ldg(&g_packed[vi.w]);
            float4 pj3 = __ldg(&g_packed[vj.w]);
            acc += edge_contrib(pi2, pj2, vi.z, vj.z, s_zpow, s_par);
            acc += edge_contrib(pi3, pj3, vi.w, vj.w, s_zpow, s_par);
        }
    }

    // warp reduce
    #pragma unroll
    for (int off = 16; off; off >>= 1)
        acc += __shfl_xor_sync(0xffffffffu, acc, off);
    if ((tid & 31) == 0) s_red[tid >> 5] = acc;
    __syncthreads();
    if (tid < 8) {
        float v = s_red[tid];
        #pragma unroll
        for (int off = 4; off; off >>= 1)
            v += __shfl_xor_sync(0xffu, v, off);
        if (tid == 0) atomicAdd(out, v * s_par[9]);
    }
}

extern "C" void kernel_launch(void* const* d_in, const int* in_sizes, int n_in,
                              void* d_out, int out_size) {
    const float* R            = (const float*)d_in[0];
    const int*   Z            = (const int*)  d_in[1];
    const int*   idx          = (const int*)  d_in[2];
    const float* a_exp        = (const float*)d_in[3];
    const float* a_num        = (const float*)d_in[4];
    const float* coefficients = (const float*)d_in[5];
    const float* exponents    = (const float*)d_in[6];
    const float* rep_scale    = (const float*)d_in[7];
    float* out = (float*)d_out;

    int nAtoms = in_sizes[1];
    int nE     = in_sizes[2] / 2;  // idx is [2, E] row-major

    // Max-L1 carveout for the gather kernel (host-side attribute, not a
    // stream op — graph-capture legal; idempotent across replays).
    static bool carveout_set = false;
    if (!carveout_set) {
        cudaFuncSetAttribute(edge_kernel,
                             cudaFuncAttributePreferredSharedMemoryCarveout,
                             cudaSharedmemCarveoutMaxL1);
        carveout_set = true;
    }

    prepass_kernel<<<(nAtoms + 255) / 256, 256>>>(
        R, Z, a_exp, a_num, coefficients, exponents, rep_scale, out, nAtoms);

    int nQuad = nE >> 2;
    edge_kernel<<<(nQuad + 255) / 256, 256>>>(idx, idx + nE, out, nQuad);
}

// round 12
// speedup vs baseline: 1.0352x; 1.0352x over previous
#include <cuda_runtime.h>
#include <math.h>

#define KE_CONST 14.3996f
#define MAX_ATOMS 131072

// Scratch (no allocations allowed in kernel_launch)
__device__ float4 g_packed[MAX_ATOMS];   // x, y, z, Zf per atom
__device__ float  g_zpow[64];            // Z^softplus(a_exp) LUT
__device__ float  g_params[16];          // [0]=1/an, [1..4]=coeffs, [5..8]=exps, [9]=0.5*KE*rep_scale

__device__ __forceinline__ float softplus_f(float x) {
    return (x > 20.0f) ? x : log1pf(expf(x));
}

__global__ void prepass_kernel(const float* __restrict__ R,
                               const int*   __restrict__ Z,
                               const float* __restrict__ a_exp,
                               const float* __restrict__ a_num,
                               const float* __restrict__ coefficients,
                               const float* __restrict__ exponents,
                               const float* __restrict__ rep_scale,
                               float* __restrict__ out,
                               int nAtoms) {
    int i = blockIdx.x * blockDim.x + threadIdx.x;
    if (i < nAtoms) {
        float4 p;
        p.x = R[3 * i + 0];
        p.y = R[3 * i + 1];
        p.z = R[3 * i + 2];
        p.w = (float)Z[i];
        g_packed[i] = p;
    }
    // Parallel Z^ae LUT
    if (i < 64) {
        float ae = softplus_f(a_exp[0]);
        g_zpow[i] = (i == 0) ? 0.0f : powf((float)i, ae);
    }
    if (i == 0) {
        out[0] = 0.0f;  // d_out is poisoned; zero before atomics
        g_params[0] = 1.0f / softplus_f(a_num[0]);
        #pragma unroll
        for (int k = 0; k < 4; ++k) {
            g_params[1 + k] = softplus_f(coefficients[k]);
            g_params[5 + k] = softplus_f(exponents[k]);
        }
        g_params[9] = 0.5f * KE_CONST * softplus_f(rep_scale[0]);
    }
}

// FINAL champion configuration (measured best across R1-R11):
//  - packed float4 atom records: 1 L1tex wavefront per gather (binding
//    resource: 12.8M random gathers ~= 86.5K wavefronts/SM ~= 44-48us floor)
//  - params in SMEM, read only inside the rare (<2%) live branch -> hot
//    gather path fits regs<=32 -> 8 CTAs x 256 = 64 warps/SM
//  - 4 edges/thread as two MLP=4 gather batches
//  - many short CTAs (6250 = 5.3 waves) for work-stealing backfill
//  - d2>=36 early-out kills ~98% of MUFU work (cutoff exactly zero there)
// Measured-rejected: 32-warp/MLP-8 (R2), persistent grid (R5), block=128
// (R6), 8 edges/thread (R8), max-L1 carveout (R11: occ 87->56%, no gain).
__device__ __forceinline__ float edge_contrib(float4 pi, float4 pj, int ai, int aj,
                                              const float* __restrict__ s_zpow,
                                              const volatile float* s_par) {
    float dx = pj.x - pi.x;
    float dy = pj.y - pi.y;
    float dz = pj.z - pi.z;
    float d2 = fmaf(dx, dx, fmaf(dy, dy, dz * dz));
    if (d2 < 36.0f && ai != aj) {
        float dr = fmaxf(sqrtf(d2), 0.02f);
        float inv_dr = __fdividef(1.0f, dr);
        // cos(pi * dr / 6): pi/6 = 0.5235987755982988
        float ccut = 0.5f * (__cosf(dr * 0.5235987755982988f) + 1.0f);
        float adiv = s_zpow[(int)pi.w] + s_zpow[(int)pj.w];
        float dist = dr * adiv * s_par[0];
        float f = s_par[1] * __expf(-s_par[5] * dist)
                + s_par[2] * __expf(-s_par[6] * dist)
                + s_par[3] * __expf(-s_par[7] * dist)
                + s_par[4] * __expf(-s_par[8] * dist);
        return pi.w * pj.w * inv_dr * f * ccut;
    }
    return 0.0f;
}

__global__ __launch_bounds__(256, 8)
void edge_kernel(const int* __restrict__ idx_i,
                 const int* __restrict__ idx_j,
                 float* __restrict__ out,
                 int nQuad) {
    __shared__ float s_zpow[64];
    __shared__ float s_par[10];
    __shared__ float s_red[8];

    int tid = threadIdx.x;
    if (tid < 64) s_zpow[tid] = g_zpow[tid];
    if (tid < 10) s_par[tid] = g_params[tid];
    __syncthreads();

    float acc = 0.0f;
    int t = blockIdx.x * 256 + tid;

    if (t < nQuad) {
        int4 vi = __ldg(((const int4*)idx_i) + t);
        int4 vj = __ldg(((const int4*)idx_j) + t);

        // Batch of 4 gathers in flight before any compute
        {
            float4 pi0 = __ldg(&g_packed[vi.x]);
            float4 pj0 = __ldg(&g_packed[vj.x]);
            float4 pi1 = __ldg(&g_packed[vi.y]);
            float4 pj1 = __ldg(&g_packed[vj.y]);
            acc += edge_contrib(pi0, pj0, vi.x, vj.x, s_zpow, s_par);
            acc += edge_contrib(pi1, pj1, vi.y, vj.y, s_zpow, s_par);
        }
        {
            float4 pi2 = __ldg(&g_packed[vi.z]);
            float4 pj2 = __ldg(&g_packed[vj.z]);
            float4 pi3 = __ldg(&g_packed[vi.w]);
            float4 pj3 = __ldg(&g_packed[vj.w]);
            acc += edge_contrib(pi2, pj2, vi.z, vj.z, s_zpow, s_par);
            acc += edge_contrib(pi3, pj3, vi.w, vj.w, s_zpow, s_par);
        }
    }

    // warp reduce
    #pragma unroll
    for (int off = 16; off; off >>= 1)
        acc += __shfl_xor_sync(0xffffffffu, acc, off);
    if ((tid & 31) == 0) s_red[tid >> 5] = acc;
    __syncthreads();
    if (tid < 8) {
        float v = s_red[tid];
        #pragma unroll
        for (int off = 4; off; off >>= 1)
            v += __shfl_xor_sync(0xffu, v, off);
        if (tid == 0) atomicAdd(out, v * s_par[9]);
    }
}

extern "C" void kernel_launch(void* const* d_in, const int* in_sizes, int n_in,
                              void* d_out, int out_size) {
    const float* R            = (const float*)d_in[0];
    const int*   Z            = (const int*)  d_in[1];
    const int*   idx          = (const int*)  d_in[2];
    const float* a_exp        = (const float*)d_in[3];
    const float* a_num        = (const float*)d_in[4];
    const float* coefficients = (const float*)d_in[5];
    const float* exponents    = (const float*)d_in[6];
    const float* rep_scale    = (const float*)d_in[7];
    float* out = (float*)d_out;

    int nAtoms = in_sizes[1];
    int nE     = in_sizes[2] / 2;  // idx is [2, E] row-major

    prepass_kernel<<<(nAtoms + 255) / 256, 256>>>(
        R, Z, a_exp, a_num, coefficients, exponents, rep_scale, out, nAtoms);

    int nQuad = nE >> 2;
    edge_kernel<<<(nQuad + 255) / 256, 256>>>(idx, idx + nE, out, nQuad);
}